// round 15
// baseline (speedup 1.0000x reference)
#include <cuda_runtime.h>
#include <cuda_fp16.h>
#include <cstdint>

namespace {
constexpr int B_ = 32, S_ = 500, C_ = 1024, H_ = 16, D_ = 64;
constexpr int BH_ = B_ * H_;   // 512
constexpr int M_  = B_ * S_;   // 16000

// fp16 GEMM: CTA tile 256x128, BK=64. Stage: [A 32K][B 16K]=48KB, 3 stages.
constexpr int OFF_A = 0;
constexpr int OFF_B = 32768;
constexpr int STAGE = 49152;
constexpr int NST   = 3;
constexpr int GSMEM = STAGE * NST;   // 144KB
constexpr int MT    = 63;            // ceil(16000/256) m-tiles

// Attention: q-tile 64 rows, 4 warps. Stage holds 128 kv rows: [K 16K][V 16K].
constexpr int AQ   = 0;
constexpr int AKV0 = 8192;
constexpr int AKV_STRIDE = 32768;
constexpr int ASMEM = AKV0 + 2 * AKV_STRIDE;  // 72KB

constexpr float LOG2E = 1.4426950408889634f;
constexpr uint32_t ONE2 = 0x3C003C00u;   // half2(1.0, 1.0)
}

// Scratch (__device__ globals: allocation-free rule)
__device__ __align__(128) __half g_qh[(size_t)BH_ * S_ * D_];
__device__ __align__(128) __half g_kh[(size_t)BH_ * S_ * D_];
__device__ __align__(128) __half g_vh[(size_t)BH_ * S_ * D_];
__device__ __align__(128) __half g_xh[(size_t)M_ * C_];
__device__ __align__(128) __half g_yh[(size_t)M_ * C_];
__device__ __align__(128) __half g_wh[4u * 1024u * 1024u];   // W^T fp16 [z][n][k]

// ---------------------------------------------------------------------------
// helpers
// ---------------------------------------------------------------------------
static __device__ __forceinline__ uint32_t s2u(const void* p) {
    uint32_t a;
    asm("{ .reg .u64 t; cvta.to.shared.u64 t, %1; cvt.u32.u64 %0, t; }"
        : "=r"(a) : "l"(p));
    return a;
}
static __device__ __forceinline__ uint32_t swz(uint32_t o) {
    return o ^ ((o >> 3) & 0x70u);
}
static __device__ __forceinline__ void cpa16(uint32_t s, const void* g) {
    asm volatile("cp.async.cg.shared.global [%0], [%1], 16;" :: "r"(s), "l"(g));
}
static __device__ __forceinline__ void cpa16z(uint32_t s, const void* g, uint32_t sz) {
    asm volatile("cp.async.cg.shared.global [%0], [%1], 16, %2;"
                 :: "r"(s), "l"(g), "r"(sz));
}

#define LDSM4(r0, r1, r2, r3, a) \
    asm volatile("ldmatrix.sync.aligned.m8n8.x4.shared.b16 {%0,%1,%2,%3}, [%4];" \
                 : "=r"(r0), "=r"(r1), "=r"(r2), "=r"(r3) : "r"(a))
#define LDSM4T(r0, r1, r2, r3, a) \
    asm volatile("ldmatrix.sync.aligned.m8n8.x4.trans.shared.b16 {%0,%1,%2,%3}, [%4];" \
                 : "=r"(r0), "=r"(r1), "=r"(r2), "=r"(r3) : "r"(a))

#define MMA_F16(d, a, b0, b1) \
    asm volatile( \
        "mma.sync.aligned.m16n8k16.row.col.f32.f16.f16.f32 " \
        "{%0,%1,%2,%3}, {%4,%5,%6,%7}, {%8,%9}, {%0,%1,%2,%3};" \
        : "+f"((d)[0]), "+f"((d)[1]), "+f"((d)[2]), "+f"((d)[3]) \
        : "r"((a)[0]), "r"((a)[1]), "r"((a)[2]), "r"((a)[3]), \
          "r"(b0), "r"(b1))

// ---------------------------------------------------------------------------
// fp16 GEMM core: C[256x128] = A[256x1024] * B^T (B stored [n][k] fp16).
// 512 threads / 16 warps (4m x 4n), warp tile 64x32, BK=64, 3-stage.
// Next-stage loads split: A-half at kk0, B-half + commit at kk1.
// ---------------------------------------------------------------------------
static __device__ __forceinline__ void load_stage_a(
    uint32_t sb, int buf, const __half* __restrict__ A,
    int m0, int k0, int tid)
{
    const uint32_t base = sb + buf * STAGE;
    const int ra = tid >> 1;
    const int ha = tid & 1;
    const int mrow = m0 + ra;
    const uint32_t sza = (mrow < M_) ? 16u : 0u;
    const size_t ga = (size_t)(mrow < M_ ? mrow : 0) * C_ + k0 + ha * 32;
#pragma unroll
    for (int i = 0; i < 4; i++) {
        const uint32_t so = swz((uint32_t)(ra * 128 + ha * 64 + i * 16));
        cpa16z(base + OFF_A + so, A + ga + i * 8, sza);
    }
}
static __device__ __forceinline__ void load_stage_b(
    uint32_t sb, int buf, const __half* __restrict__ Bt,
    int n0, int k0, int tid)
{
    const uint32_t base = sb + buf * STAGE;
    const int rb = tid >> 2;
    const int qb = tid & 3;
    const size_t gb = (size_t)(n0 + rb) * C_ + k0 + qb * 16;   // halfs (32B)
#pragma unroll
    for (int i = 0; i < 2; i++) {
        const uint32_t so = swz((uint32_t)(rb * 128 + qb * 32 + i * 16));
        cpa16(base + OFF_B + so, Bt + gb + i * 8);
    }
}

static __device__ __forceinline__ void gemm_core(
    uint32_t sb, const __half* A, const __half* Bt,
    int m0, int n0, float acc[4][4][4])
{
    const int tid = threadIdx.x;
    const int wid = tid >> 5, lane = tid & 31;
    const int wm = wid >> 2, wn = wid & 3;

    const uint32_t arow  = wm * 64 + (lane & 15);
    const uint32_t acolk = (lane & 16) ? 16u : 0u;
    const uint32_t brow  = wn * 32 + (lane & 7) + ((lane & 16) ? 8u : 0u);
    const uint32_t bcolk = (lane & 8) ? 16u : 0u;

#pragma unroll
    for (int mt = 0; mt < 4; mt++)
#pragma unroll
        for (int nf = 0; nf < 4; nf++)
#pragma unroll
            for (int j = 0; j < 4; j++) acc[mt][nf][j] = 0.f;

    load_stage_a(sb, 0, A, m0, 0, tid);
    load_stage_b(sb, 0, Bt, n0, 0, tid);
    asm volatile("cp.async.commit_group;" ::: "memory");
    load_stage_a(sb, 1, A, m0, 64, tid);
    load_stage_b(sb, 1, Bt, n0, 64, tid);
    asm volatile("cp.async.commit_group;" ::: "memory");

    for (int s = 0; s < 16; s++) {
        asm volatile("cp.async.wait_group 1;" ::: "memory");
        __syncthreads();
        const uint32_t base = sb + (s % NST) * STAGE;

#pragma unroll
        for (int kk = 0; kk < 4; kk++) {
            const uint32_t ac = kk * 32 + acolk;
            const uint32_t bc = kk * 32 + bcolk;
            uint32_t ah[4][4], bh[2][4];
#pragma unroll
            for (int mt = 0; mt < 4; mt++) {
                const uint32_t off = swz((arow + mt * 16) * 128 + ac);
                LDSM4(ah[mt][0], ah[mt][1], ah[mt][2], ah[mt][3],
                      base + OFF_A + off);
            }
#pragma unroll
            for (int ng = 0; ng < 2; ng++) {
                const uint32_t off = swz((brow + ng * 16) * 128 + bc);
                LDSM4(bh[ng][0], bh[ng][1], bh[ng][2], bh[ng][3],
                      base + OFF_B + off);
            }
#pragma unroll
            for (int ng = 0; ng < 2; ng++)
#pragma unroll
                for (int mt = 0; mt < 4; mt++) {
                    MMA_F16(acc[mt][2 * ng],     ah[mt], bh[ng][0], bh[ng][1]);
                    MMA_F16(acc[mt][2 * ng + 1], ah[mt], bh[ng][2], bh[ng][3]);
                }
            if (kk == 0 && s + 2 < 16)
                load_stage_a(sb, (s + 2) % NST, A, m0, (s + 2) * 64, tid);
            if (kk == 1) {
                if (s + 2 < 16)
                    load_stage_b(sb, (s + 2) % NST, Bt, n0, (s + 2) * 64, tid);
                asm volatile("cp.async.commit_group;" ::: "memory");
            }
        }
    }
}

// ---------------------------------------------------------------------------
// QKV projection: epilogue writes plain fp16 q/k/v [B,H,S,D];
// Q scaled by (1/8)*log2(e) for exp2-domain softmax.
// ---------------------------------------------------------------------------
__global__ __launch_bounds__(512, 1) void qkv_mma(
    const float* __restrict__ bq, const float* __restrict__ bk,
    const float* __restrict__ bv)
{
    extern __shared__ __align__(1024) char dsm[];
    const uint32_t sb = s2u(dsm);
    const int tid = threadIdx.x, wid = tid >> 5, lane = tid & 31;
    const int wm = wid >> 2, wn = wid & 3;

    const int which = blockIdx.z;
    const __half* Bt = g_wh + ((size_t)which << 20);
    const float* bias = (which == 0) ? bq : (which == 1) ? bk : bv;
    __half* dst = (which == 0) ? g_qh : (which == 1) ? g_kh : g_vh;
    const float scale = (which == 0) ? 0.125f * LOG2E : 1.0f;

    const int m0 = blockIdx.y * 256, n0 = blockIdx.x * 128;
    float acc[4][4][4];
    gemm_core(sb, g_xh, Bt, m0, n0, acc);

    const int qr = lane >> 2, qc = (lane & 3) * 2;
#pragma unroll
    for (int mt = 0; mt < 4; mt++) {
        const int mr0 = m0 + wm * 64 + mt * 16 + qr;
        const int mr1 = mr0 + 8;
        const int b0 = mr0 / S_, s0 = mr0 - b0 * S_;
        const int b1 = mr1 / S_, s1 = mr1 - b1 * S_;
#pragma unroll
        for (int nf = 0; nf < 4; nf++) {
            const int c = n0 + wn * 32 + nf * 8 + qc;
            const int h = c >> 6, dc = c & 63;
            const float bx = bias[c], by = bias[c + 1];
            if (mr0 < M_) {
                size_t i0 = ((size_t)(b0 * H_ + h) * S_ + s0) * D_ + dc;
                *(__half2*)(dst + i0) =
                    __floats2half2_rn((acc[mt][nf][0] + bx) * scale,
                                      (acc[mt][nf][1] + by) * scale);
            }
            if (mr1 < M_) {
                size_t i1 = ((size_t)(b1 * H_ + h) * S_ + s1) * D_ + dc;
                *(__half2*)(dst + i1) =
                    __floats2half2_rn((acc[mt][nf][2] + bx) * scale,
                                      (acc[mt][nf][3] + by) * scale);
            }
        }
    }
}

// ---------------------------------------------------------------------------
// Output projection: reads y fp16, writes d_out row-major fp32
// ---------------------------------------------------------------------------
__global__ __launch_bounds__(512, 1) void proj_mma(
    const float* __restrict__ bp, float* __restrict__ out)
{
    extern __shared__ __align__(1024) char dsm[];
    const uint32_t sb = s2u(dsm);
    const int tid = threadIdx.x, wid = tid >> 5, lane = tid & 31;
    const int wm = wid >> 2, wn = wid & 3;

    const __half* Bt = g_wh + ((size_t)3 << 20);

    const int m0 = blockIdx.y * 256, n0 = blockIdx.x * 128;
    float acc[4][4][4];
    gemm_core(sb, g_yh, Bt, m0, n0, acc);

    const int qr = lane >> 2, qc = (lane & 3) * 2;
#pragma unroll
    for (int mt = 0; mt < 4; mt++) {
        const int mr0 = m0 + wm * 64 + mt * 16 + qr;
#pragma unroll
        for (int nf = 0; nf < 4; nf++) {
            const int c = n0 + wn * 32 + nf * 8 + qc;
            const float bx = bp[c], by = bp[c + 1];
            if (mr0 < M_)
                *(float2*)(out + (size_t)mr0 * C_ + c) =
                    make_float2(acc[mt][nf][0] + bx, acc[mt][nf][1] + by);
            if (mr0 + 8 < M_)
                *(float2*)(out + (size_t)(mr0 + 8) * C_ + c) =
                    make_float2(acc[mt][nf][2] + bx, acc[mt][nf][3] + by);
        }
    }
}

// ---------------------------------------------------------------------------
// Pre-passes: x -> fp16 ; W transpose -> fp16 [n][k]
// ---------------------------------------------------------------------------
__global__ void xcvt_kernel(const float* __restrict__ x)
{
    const size_t i = ((size_t)blockIdx.x * 256 + threadIdx.x) * 8;
    float4 v0 = *(const float4*)(x + i);
    float4 v1 = *(const float4*)(x + i + 4);
    *(__half2*)(g_xh + i)     = __floats2half2_rn(v0.x, v0.y);
    *(__half2*)(g_xh + i + 2) = __floats2half2_rn(v0.z, v0.w);
    *(__half2*)(g_xh + i + 4) = __floats2half2_rn(v1.x, v1.y);
    *(__half2*)(g_xh + i + 6) = __floats2half2_rn(v1.z, v1.w);
}

__global__ void wtrans_kernel(
    const float* __restrict__ Wq, const float* __restrict__ Wk,
    const float* __restrict__ Wv, const float* __restrict__ Wp)
{
    __shared__ float t[32][33];
    const int z = blockIdx.z;
    const float* src = (z == 0) ? Wq : (z == 1) ? Wk : (z == 2) ? Wv : Wp;
    __half* dst = g_wh + ((size_t)z << 20);
    const int x0 = blockIdx.x * 32, y0 = blockIdx.y * 32;
    const int tx = threadIdx.x, ty = threadIdx.y;
#pragma unroll
    for (int i = 0; i < 32; i += 8)
        t[ty + i][tx] = src[(size_t)(y0 + ty + i) * 1024 + x0 + tx];
    __syncthreads();
#pragma unroll
    for (int i = 0; i < 32; i += 8)
        dst[(size_t)(x0 + ty + i) * 1024 + y0 + tx] = __float2half(t[tx][ty + i]);
}

// ---------------------------------------------------------------------------
// Flash attention: fp16 single, h2exp2 softmax, l-via-MMA.
// R15: 128 kv rows per smem stage (2 sub-tiles) -> half the syncs/loads.
// ---------------------------------------------------------------------------
static __device__ __forceinline__ void attn_load_kv(
    uint32_t sb, int buf, size_t boff, int st, int tid)
{
    const int r = tid;                 // 0..127 kv rows of this stage
    const int kpos = st * 128 + r;
    const uint32_t sz = (kpos < S_) ? 16u : 0u;
    const int kc = (kpos < S_) ? kpos : (S_ - 1);
    const uint32_t base = sb + AKV0 + buf * AKV_STRIDE;
    const size_t g = boff + (size_t)kc * D_;
#pragma unroll
    for (int i = 0; i < 8; i++) {
        const uint32_t sw = swz((uint32_t)(r * 128 + i * 16));
        cpa16z(base + sw, g_kh + g + i * 8, sz);            // K @ +0
        cpa16z(base + 16384 + sw, g_vh + g + i * 8, sz);    // V @ +16KB
    }
}

__global__ __launch_bounds__(128) void attn_mma()
{
    extern __shared__ __align__(1024) char asm_[];
    const uint32_t sb = s2u(asm_);
    const int tid = threadIdx.x, wid = tid >> 5, lane = tid & 31;
    const int qt = blockIdx.x, bh = blockIdx.y;
    const size_t boff = (size_t)bh * (S_ * D_);
    const int nst = (qt + 2) >> 1;     // 128-row kv stages

    {
        const int r = tid >> 1;
        const int hf = tid & 1;
        const int qpos = qt * 64 + r;
        const bool ok = qpos < S_;
        const size_t g = boff + (size_t)(ok ? qpos : 0) * D_;
#pragma unroll
        for (int i = 0; i < 4; i++) {
            const int chunk = hf * 4 + i;
            const uint32_t sw = swz((uint32_t)(r * 128 + chunk * 16));
            float4 v = make_float4(0, 0, 0, 0);
            if (ok) v = *(const float4*)(g_qh + g + chunk * 8);
            *(float4*)(asm_ + AQ + sw) = v;
        }
    }
    attn_load_kv(sb, 0, boff, 0, tid);
    asm volatile("cp.async.commit_group;" ::: "memory");
    __syncthreads();

    uint32_t qf[4][4];
    {
        const uint32_t arow = wid * 16 + (lane & 15);
        const uint32_t ack  = (lane & 16) ? 16u : 0u;
#pragma unroll
        for (int kk = 0; kk < 4; kk++) {
            uint32_t off = swz(arow * 128 + kk * 32 + ack);
            LDSM4(qf[kk][0], qf[kk][1], qf[kk][2], qf[kk][3], sb + AQ + off);
        }
    }

    float o[8][4];
#pragma unroll
    for (int dn = 0; dn < 8; dn++)
#pragma unroll
        for (int j = 0; j < 4; j++) o[dn][j] = 0.f;
    float lsum[4] = {0.f, 0.f, 0.f, 0.f};
    float m0v = -1e30f, m1v = -1e30f;

    const int row0 = qt * 64 + wid * 16 + (lane >> 2);
    const int row1 = row0 + 8;

    const uint32_t brow = (lane & 7) + ((lane & 16) ? 8u : 0u);
    const uint32_t bck  = (lane & 8) ? 16u : 0u;
    const uint32_t vrow = (lane & 7) + ((lane & 8) ? 8u : 0u);
    const uint32_t vck  = (lane & 16) ? 16u : 0u;

    for (int st = 0; st < nst; st++) {
        const int buf = st & 1;
        __syncthreads();
        if (st + 1 < nst) {
            attn_load_kv(sb, buf ^ 1, boff, st + 1, tid);
            asm volatile("cp.async.commit_group;" ::: "memory");
            asm volatile("cp.async.wait_group 1;" ::: "memory");
        } else {
            asm volatile("cp.async.wait_group 0;" ::: "memory");
        }
        __syncthreads();

        const uint32_t stb = sb + AKV0 + buf * AKV_STRIDE;

#pragma unroll
        for (int sub = 0; sub < 2; sub++) {
            const int kt = st * 2 + sub;
            if (kt > qt) break;
            const uint32_t kvK = stb + sub * 8192;
            const uint32_t kvV = stb + 16384 + sub * 8192;

            // ---- S = Q @ K^T ----
            float sc[8][4];
#pragma unroll
            for (int j = 0; j < 8; j++)
#pragma unroll
                for (int q = 0; q < 4; q++) sc[j][q] = 0.f;

#pragma unroll
            for (int kk = 0; kk < 4; kk++) {
#pragma unroll
                for (int j2 = 0; j2 < 4; j2++) {
                    uint32_t off = swz((j2 * 16 + brow) * 128 + kk * 32 + bck);
                    uint32_t kh[4];
                    LDSM4(kh[0], kh[1], kh[2], kh[3], kvK + off);
                    MMA_F16(sc[2 * j2],     qf[kk], kh[0], kh[1]);
                    MMA_F16(sc[2 * j2 + 1], qf[kk], kh[2], kh[3]);
                }
            }

            // ---- mask ----
            if ((kt == qt) || ((kt + 1) * 64 > S_)) {
                const int cb = kt * 64 + (lane & 3) * 2;
#pragma unroll
                for (int j = 0; j < 8; j++) {
                    const int c0 = cb + j * 8, c1 = c0 + 1;
                    if (c0 > row0 || c0 >= S_) sc[j][0] = -1e30f;
                    if (c1 > row0 || c1 >= S_) sc[j][1] = -1e30f;
                    if (c0 > row1 || c0 >= S_) sc[j][2] = -1e30f;
                    if (c1 > row1 || c1 >= S_) sc[j][3] = -1e30f;
                }
            }

            // ---- online softmax (exp2 domain) ----
            float mt0 = -1e30f, mt1 = -1e30f;
#pragma unroll
            for (int j = 0; j < 8; j++) {
                mt0 = fmaxf(mt0, fmaxf(sc[j][0], sc[j][1]));
                mt1 = fmaxf(mt1, fmaxf(sc[j][2], sc[j][3]));
            }
            mt0 = fmaxf(mt0, __shfl_xor_sync(0xffffffffu, mt0, 1));
            mt0 = fmaxf(mt0, __shfl_xor_sync(0xffffffffu, mt0, 2));
            mt1 = fmaxf(mt1, __shfl_xor_sync(0xffffffffu, mt1, 1));
            mt1 = fmaxf(mt1, __shfl_xor_sync(0xffffffffu, mt1, 2));
            const float mn0 = fmaxf(m0v, mt0), mn1 = fmaxf(m1v, mt1);
            const float cr0 = exp2f(m0v - mn0), cr1 = exp2f(m1v - mn1);
            m0v = mn0; m1v = mn1;

            uint32_t ph[8][2];
#pragma unroll
            for (int j = 0; j < 8; j++) {
                __half2 a0 = __floats2half2_rn(sc[j][0] - mn0, sc[j][1] - mn0);
                __half2 a1 = __floats2half2_rn(sc[j][2] - mn1, sc[j][3] - mn1);
                __half2 e0 = h2exp2(a0);
                __half2 e1 = h2exp2(a1);
                ph[j][0] = *(uint32_t*)&e0;
                ph[j][1] = *(uint32_t*)&e1;
            }

            lsum[0] *= cr0; lsum[1] *= cr0; lsum[2] *= cr1; lsum[3] *= cr1;
#pragma unroll
            for (int dn = 0; dn < 8; dn++) {
                o[dn][0] *= cr0; o[dn][1] *= cr0;
                o[dn][2] *= cr1; o[dn][3] *= cr1;
            }

            // ---- l += P @ ones  and  O += P @ V ----
#pragma unroll
            for (int kk = 0; kk < 4; kk++) {
                uint32_t ah[4] = {ph[2 * kk][0], ph[2 * kk][1],
                                  ph[2 * kk + 1][0], ph[2 * kk + 1][1]};
                MMA_F16(lsum, ah, ONE2, ONE2);
#pragma unroll
                for (int dj2 = 0; dj2 < 4; dj2++) {
                    uint32_t off = swz((kk * 16 + vrow) * 128 + dj2 * 32 + vck);
                    uint32_t vh[4];
                    LDSM4T(vh[0], vh[1], vh[2], vh[3], kvV + off);
                    MMA_F16(o[2 * dj2],     ah, vh[0], vh[1]);
                    MMA_F16(o[2 * dj2 + 1], ah, vh[2], vh[3]);
                }
            }
        }
    }

    const int h = bh & (H_ - 1);
    const int b = bh >> 4;
    const float inv0 = 1.f / lsum[0], inv1 = 1.f / lsum[2];
    const int dc = (lane & 3) * 2;
#pragma unroll
    for (int dn = 0; dn < 8; dn++) {
        const int d = h * D_ + dn * 8 + dc;
        if (row0 < S_) {
            size_t i0 = (size_t)(b * S_ + row0) * C_ + d;
            *(__half2*)(g_yh + i0) = __floats2half2_rn(o[dn][0] * inv0,
                                                       o[dn][1] * inv0);
        }
        if (row1 < S_) {
            size_t i1 = (size_t)(b * S_ + row1) * C_ + d;
            *(__half2*)(g_yh + i1) = __floats2half2_rn(o[dn][2] * inv1,
                                                       o[dn][3] * inv1);
        }
    }
}

// ---------------------------------------------------------------------------
extern "C" void kernel_launch(void* const* d_in, const int* in_sizes, int n_in,
                              void* d_out, int out_size)
{
    const float* x  = (const float*)d_in[0];
    const float* Wq = (const float*)d_in[1];
    const float* bq = (const float*)d_in[2];
    const float* Wk = (const float*)d_in[3];
    const float* bk = (const float*)d_in[4];
    const float* Wv = (const float*)d_in[5];
    const float* bv = (const float*)d_in[6];
    const float* Wp = (const float*)d_in[7];
    const float* bp = (const float*)d_in[8];
    float* out = (float*)d_out;

    cudaFuncSetAttribute(qkv_mma, cudaFuncAttributeMaxDynamicSharedMemorySize, GSMEM);
    cudaFuncSetAttribute(proj_mma, cudaFuncAttributeMaxDynamicSharedMemorySize, GSMEM);
    cudaFuncSetAttribute(attn_mma, cudaFuncAttributeMaxDynamicSharedMemorySize, ASMEM);

    xcvt_kernel<<<M_ * C_ / 2048, 256>>>(x);
    wtrans_kernel<<<dim3(32, 32, 4), dim3(32, 8)>>>(Wq, Wk, Wv, Wp);
    qkv_mma<<<dim3(8, MT, 3), 512, GSMEM>>>(bq, bk, bv);
    attn_mma<<<dim3(8, BH_), 128, ASMEM>>>();
    proj_mma<<<dim3(8, MT), 512, GSMEM>>>(bp, out);
}

// round 16
// speedup vs baseline: 1.0755x; 1.0755x over previous
#include <cuda_runtime.h>
#include <cuda_fp16.h>
#include <cstdint>

namespace {
constexpr int B_ = 32, S_ = 500, C_ = 1024, H_ = 16, D_ = 64;
constexpr int BH_ = B_ * H_;   // 512
constexpr int M_  = B_ * S_;   // 16000

// fp16 GEMM: CTA tile 256x128, BK=64. Stage: [A 32K][B 16K]=48KB, 3 stages.
constexpr int OFF_A = 0;
constexpr int OFF_B = 32768;
constexpr int STAGE = 49152;
constexpr int NST   = 3;
constexpr int GSMEM = STAGE * NST;   // 144KB
constexpr int MT    = 63;            // ceil(16000/256) m-tiles

// Attention (R14 layout): q-tile 64 rows, 4 warps. Q 8K; KV stage 16K x2.
constexpr int AQ   = 0;
constexpr int AKV0 = 8192;
constexpr int AKH = 0, AVH = 8192;
constexpr int AKV_STRIDE = 16384;
constexpr int ASMEM = AKV0 + 2 * AKV_STRIDE;  // 40KB

constexpr float LOG2E = 1.4426950408889634f;
constexpr uint32_t ONE2 = 0x3C003C00u;   // half2(1.0, 1.0)
}

// Scratch (__device__ globals: allocation-free rule)
__device__ __align__(128) __half g_qh[(size_t)BH_ * S_ * D_];
__device__ __align__(128) __half g_kh[(size_t)BH_ * S_ * D_];
__device__ __align__(128) __half g_vh[(size_t)BH_ * S_ * D_];
__device__ __align__(128) __half g_xh[(size_t)M_ * C_];
__device__ __align__(128) __half g_yh[(size_t)M_ * C_];
__device__ __align__(128) __half g_wh[4u * 1024u * 1024u];   // W^T fp16 [z][n][k]

// ---------------------------------------------------------------------------
// helpers
// ---------------------------------------------------------------------------
static __device__ __forceinline__ uint32_t s2u(const void* p) {
    uint32_t a;
    asm("{ .reg .u64 t; cvta.to.shared.u64 t, %1; cvt.u32.u64 %0, t; }"
        : "=r"(a) : "l"(p));
    return a;
}
static __device__ __forceinline__ uint32_t swz(uint32_t o) {
    return o ^ ((o >> 3) & 0x70u);
}
static __device__ __forceinline__ void cpa16(uint32_t s, const void* g) {
    asm volatile("cp.async.cg.shared.global [%0], [%1], 16;" :: "r"(s), "l"(g));
}
static __device__ __forceinline__ void cpa16z(uint32_t s, const void* g, uint32_t sz) {
    asm volatile("cp.async.cg.shared.global [%0], [%1], 16, %2;"
                 :: "r"(s), "l"(g), "r"(sz));
}

#define LDSM4(r0, r1, r2, r3, a) \
    asm volatile("ldmatrix.sync.aligned.m8n8.x4.shared.b16 {%0,%1,%2,%3}, [%4];" \
                 : "=r"(r0), "=r"(r1), "=r"(r2), "=r"(r3) : "r"(a))
#define LDSM4T(r0, r1, r2, r3, a) \
    asm volatile("ldmatrix.sync.aligned.m8n8.x4.trans.shared.b16 {%0,%1,%2,%3}, [%4];" \
                 : "=r"(r0), "=r"(r1), "=r"(r2), "=r"(r3) : "r"(a))

#define MMA_F16(d, a, b0, b1) \
    asm volatile( \
        "mma.sync.aligned.m16n8k16.row.col.f32.f16.f16.f32 " \
        "{%0,%1,%2,%3}, {%4,%5,%6,%7}, {%8,%9}, {%0,%1,%2,%3};" \
        : "+f"((d)[0]), "+f"((d)[1]), "+f"((d)[2]), "+f"((d)[3]) \
        : "r"((a)[0]), "r"((a)[1]), "r"((a)[2]), "r"((a)[3]), \
          "r"(b0), "r"(b1))

// ---------------------------------------------------------------------------
// fp16 GEMM core: C[256x128] = A[256x1024] * B^T (B stored [n][k] fp16).
// 512 threads / 16 warps (4m x 4n), warp tile 64x32, BK=64, 3-stage.
// Next-stage loads split: A-half at kk0, B-half + commit at kk1.
// ---------------------------------------------------------------------------
static __device__ __forceinline__ void load_stage_a(
    uint32_t sb, int buf, const __half* __restrict__ A,
    int m0, int k0, int tid)
{
    const uint32_t base = sb + buf * STAGE;
    const int ra = tid >> 1;
    const int ha = tid & 1;
    const int mrow = m0 + ra;
    const uint32_t sza = (mrow < M_) ? 16u : 0u;
    const size_t ga = (size_t)(mrow < M_ ? mrow : 0) * C_ + k0 + ha * 32;
#pragma unroll
    for (int i = 0; i < 4; i++) {
        const uint32_t so = swz((uint32_t)(ra * 128 + ha * 64 + i * 16));
        cpa16z(base + OFF_A + so, A + ga + i * 8, sza);
    }
}
static __device__ __forceinline__ void load_stage_b(
    uint32_t sb, int buf, const __half* __restrict__ Bt,
    int n0, int k0, int tid)
{
    const uint32_t base = sb + buf * STAGE;
    const int rb = tid >> 2;
    const int qb = tid & 3;
    const size_t gb = (size_t)(n0 + rb) * C_ + k0 + qb * 16;   // halfs (32B)
#pragma unroll
    for (int i = 0; i < 2; i++) {
        const uint32_t so = swz((uint32_t)(rb * 128 + qb * 32 + i * 16));
        cpa16(base + OFF_B + so, Bt + gb + i * 8);
    }
}

static __device__ __forceinline__ void gemm_core(
    uint32_t sb, const __half* A, const __half* Bt,
    int m0, int n0, float acc[4][4][4])
{
    const int tid = threadIdx.x;
    const int wid = tid >> 5, lane = tid & 31;
    const int wm = wid >> 2, wn = wid & 3;

    const uint32_t arow  = wm * 64 + (lane & 15);
    const uint32_t acolk = (lane & 16) ? 16u : 0u;
    const uint32_t brow  = wn * 32 + (lane & 7) + ((lane & 16) ? 8u : 0u);
    const uint32_t bcolk = (lane & 8) ? 16u : 0u;

#pragma unroll
    for (int mt = 0; mt < 4; mt++)
#pragma unroll
        for (int nf = 0; nf < 4; nf++)
#pragma unroll
            for (int j = 0; j < 4; j++) acc[mt][nf][j] = 0.f;

    load_stage_a(sb, 0, A, m0, 0, tid);
    load_stage_b(sb, 0, Bt, n0, 0, tid);
    asm volatile("cp.async.commit_group;" ::: "memory");
    load_stage_a(sb, 1, A, m0, 64, tid);
    load_stage_b(sb, 1, Bt, n0, 64, tid);
    asm volatile("cp.async.commit_group;" ::: "memory");

    for (int s = 0; s < 16; s++) {
        asm volatile("cp.async.wait_group 1;" ::: "memory");
        __syncthreads();
        const uint32_t base = sb + (s % NST) * STAGE;

#pragma unroll
        for (int kk = 0; kk < 4; kk++) {
            const uint32_t ac = kk * 32 + acolk;
            const uint32_t bc = kk * 32 + bcolk;
            uint32_t ah[4][4], bh[2][4];
#pragma unroll
            for (int mt = 0; mt < 4; mt++) {
                const uint32_t off = swz((arow + mt * 16) * 128 + ac);
                LDSM4(ah[mt][0], ah[mt][1], ah[mt][2], ah[mt][3],
                      base + OFF_A + off);
            }
#pragma unroll
            for (int ng = 0; ng < 2; ng++) {
                const uint32_t off = swz((brow + ng * 16) * 128 + bc);
                LDSM4(bh[ng][0], bh[ng][1], bh[ng][2], bh[ng][3],
                      base + OFF_B + off);
            }
#pragma unroll
            for (int ng = 0; ng < 2; ng++)
#pragma unroll
                for (int mt = 0; mt < 4; mt++) {
                    MMA_F16(acc[mt][2 * ng],     ah[mt], bh[ng][0], bh[ng][1]);
                    MMA_F16(acc[mt][2 * ng + 1], ah[mt], bh[ng][2], bh[ng][3]);
                }
            if (kk == 0 && s + 2 < 16)
                load_stage_a(sb, (s + 2) % NST, A, m0, (s + 2) * 64, tid);
            if (kk == 1) {
                if (s + 2 < 16)
                    load_stage_b(sb, (s + 2) % NST, Bt, n0, (s + 2) * 64, tid);
                asm volatile("cp.async.commit_group;" ::: "memory");
            }
        }
    }
}

// ---------------------------------------------------------------------------
// QKV projection: epilogue writes plain fp16 q/k/v [B,H,S,D];
// Q scaled by (1/8)*log2(e) for exp2-domain softmax.
// ---------------------------------------------------------------------------
__global__ __launch_bounds__(512, 1) void qkv_mma(
    const float* __restrict__ bq, const float* __restrict__ bk,
    const float* __restrict__ bv)
{
    extern __shared__ __align__(1024) char dsm[];
    const uint32_t sb = s2u(dsm);
    const int tid = threadIdx.x, wid = tid >> 5, lane = tid & 31;
    const int wm = wid >> 2, wn = wid & 3;

    const int which = blockIdx.z;
    const __half* Bt = g_wh + ((size_t)which << 20);
    const float* bias = (which == 0) ? bq : (which == 1) ? bk : bv;
    __half* dst = (which == 0) ? g_qh : (which == 1) ? g_kh : g_vh;
    const float scale = (which == 0) ? 0.125f * LOG2E : 1.0f;

    const int m0 = blockIdx.y * 256, n0 = blockIdx.x * 128;
    float acc[4][4][4];
    gemm_core(sb, g_xh, Bt, m0, n0, acc);

    const int qr = lane >> 2, qc = (lane & 3) * 2;
#pragma unroll
    for (int mt = 0; mt < 4; mt++) {
        const int mr0 = m0 + wm * 64 + mt * 16 + qr;
        const int mr1 = mr0 + 8;
        const int b0 = mr0 / S_, s0 = mr0 - b0 * S_;
        const int b1 = mr1 / S_, s1 = mr1 - b1 * S_;
#pragma unroll
        for (int nf = 0; nf < 4; nf++) {
            const int c = n0 + wn * 32 + nf * 8 + qc;
            const int h = c >> 6, dc = c & 63;
            const float bx = bias[c], by = bias[c + 1];
            if (mr0 < M_) {
                size_t i0 = ((size_t)(b0 * H_ + h) * S_ + s0) * D_ + dc;
                *(__half2*)(dst + i0) =
                    __floats2half2_rn((acc[mt][nf][0] + bx) * scale,
                                      (acc[mt][nf][1] + by) * scale);
            }
            if (mr1 < M_) {
                size_t i1 = ((size_t)(b1 * H_ + h) * S_ + s1) * D_ + dc;
                *(__half2*)(dst + i1) =
                    __floats2half2_rn((acc[mt][nf][2] + bx) * scale,
                                      (acc[mt][nf][3] + by) * scale);
            }
        }
    }
}

// ---------------------------------------------------------------------------
// Output projection: reads y fp16, writes d_out row-major fp32
// ---------------------------------------------------------------------------
__global__ __launch_bounds__(512, 1) void proj_mma(
    const float* __restrict__ bp, float* __restrict__ out)
{
    extern __shared__ __align__(1024) char dsm[];
    const uint32_t sb = s2u(dsm);
    const int tid = threadIdx.x, wid = tid >> 5, lane = tid & 31;
    const int wm = wid >> 2, wn = wid & 3;

    const __half* Bt = g_wh + ((size_t)3 << 20);

    const int m0 = blockIdx.y * 256, n0 = blockIdx.x * 128;
    float acc[4][4][4];
    gemm_core(sb, g_yh, Bt, m0, n0, acc);

    const int qr = lane >> 2, qc = (lane & 3) * 2;
#pragma unroll
    for (int mt = 0; mt < 4; mt++) {
        const int mr0 = m0 + wm * 64 + mt * 16 + qr;
#pragma unroll
        for (int nf = 0; nf < 4; nf++) {
            const int c = n0 + wn * 32 + nf * 8 + qc;
            const float bx = bp[c], by = bp[c + 1];
            if (mr0 < M_)
                *(float2*)(out + (size_t)mr0 * C_ + c) =
                    make_float2(acc[mt][nf][0] + bx, acc[mt][nf][1] + by);
            if (mr0 + 8 < M_)
                *(float2*)(out + (size_t)(mr0 + 8) * C_ + c) =
                    make_float2(acc[mt][nf][2] + bx, acc[mt][nf][3] + by);
        }
    }
}

// ---------------------------------------------------------------------------
// Pre-passes: x -> fp16 ; W transpose -> fp16 [n][k]
// ---------------------------------------------------------------------------
__global__ void xcvt_kernel(const float* __restrict__ x)
{
    const size_t i = ((size_t)blockIdx.x * 256 + threadIdx.x) * 8;
    float4 v0 = *(const float4*)(x + i);
    float4 v1 = *(const float4*)(x + i + 4);
    *(__half2*)(g_xh + i)     = __floats2half2_rn(v0.x, v0.y);
    *(__half2*)(g_xh + i + 2) = __floats2half2_rn(v0.z, v0.w);
    *(__half2*)(g_xh + i + 4) = __floats2half2_rn(v1.x, v1.y);
    *(__half2*)(g_xh + i + 6) = __floats2half2_rn(v1.z, v1.w);
}

__global__ void wtrans_kernel(
    const float* __restrict__ Wq, const float* __restrict__ Wk,
    const float* __restrict__ Wv, const float* __restrict__ Wp)
{
    __shared__ float t[32][33];
    const int z = blockIdx.z;
    const float* src = (z == 0) ? Wq : (z == 1) ? Wk : (z == 2) ? Wv : Wp;
    __half* dst = g_wh + ((size_t)z << 20);
    const int x0 = blockIdx.x * 32, y0 = blockIdx.y * 32;
    const int tx = threadIdx.x, ty = threadIdx.y;
#pragma unroll
    for (int i = 0; i < 32; i += 8)
        t[ty + i][tx] = src[(size_t)(y0 + ty + i) * 1024 + x0 + tx];
    __syncthreads();
#pragma unroll
    for (int i = 0; i < 32; i += 8)
        dst[(size_t)(x0 + ty + i) * 1024 + y0 + tx] = __float2half(t[tx][ty + i]);
}

// ---------------------------------------------------------------------------
// Flash attention (R14, reverted): fp16 single, h2exp2 softmax, l-via-MMA,
// 64-row KV stages.
// ---------------------------------------------------------------------------
static __device__ __forceinline__ void attn_load_kv(
    uint32_t sb, int buf, size_t boff, int kt, int tid)
{
    const int r = tid >> 1;
    const int hf = tid & 1;
    const int kpos = kt * 64 + r;
    const uint32_t sz = (kpos < S_) ? 16u : 0u;
    const int kc = (kpos < S_) ? kpos : (S_ - 1);
    const uint32_t base = sb + AKV0 + buf * AKV_STRIDE;
    const size_t g = boff + (size_t)kc * D_;
#pragma unroll
    for (int i = 0; i < 4; i++) {
        const int chunk = hf * 4 + i;
        const uint32_t sw = swz((uint32_t)(r * 128 + chunk * 16));
        cpa16z(base + AKH + sw, g_kh + g + chunk * 8, sz);
        cpa16z(base + AVH + sw, g_vh + g + chunk * 8, sz);
    }
}

__global__ __launch_bounds__(128) void attn_mma()
{
    extern __shared__ __align__(1024) char asm_[];
    const uint32_t sb = s2u(asm_);
    const int tid = threadIdx.x, wid = tid >> 5, lane = tid & 31;
    const int qt = blockIdx.x, bh = blockIdx.y;
    const size_t boff = (size_t)bh * (S_ * D_);

    {
        const int r = tid >> 1;
        const int hf = tid & 1;
        const int qpos = qt * 64 + r;
        const bool ok = qpos < S_;
        const size_t g = boff + (size_t)(ok ? qpos : 0) * D_;
#pragma unroll
        for (int i = 0; i < 4; i++) {
            const int chunk = hf * 4 + i;
            const uint32_t sw = swz((uint32_t)(r * 128 + chunk * 16));
            float4 v = make_float4(0, 0, 0, 0);
            if (ok) v = *(const float4*)(g_qh + g + chunk * 8);
            *(float4*)(asm_ + AQ + sw) = v;
        }
    }
    attn_load_kv(sb, 0, boff, 0, tid);
    asm volatile("cp.async.commit_group;" ::: "memory");
    __syncthreads();

    uint32_t qf[4][4];
    {
        const uint32_t arow = wid * 16 + (lane & 15);
        const uint32_t ack  = (lane & 16) ? 16u : 0u;
#pragma unroll
        for (int kk = 0; kk < 4; kk++) {
            uint32_t off = swz(arow * 128 + kk * 32 + ack);
            LDSM4(qf[kk][0], qf[kk][1], qf[kk][2], qf[kk][3], sb + AQ + off);
        }
    }

    float o[8][4];
#pragma unroll
    for (int dn = 0; dn < 8; dn++)
#pragma unroll
        for (int j = 0; j < 4; j++) o[dn][j] = 0.f;
    float lsum[4] = {0.f, 0.f, 0.f, 0.f};
    float m0v = -1e30f, m1v = -1e30f;

    const int row0 = qt * 64 + wid * 16 + (lane >> 2);
    const int row1 = row0 + 8;

    const uint32_t brow = (lane & 7) + ((lane & 16) ? 8u : 0u);
    const uint32_t bck  = (lane & 8) ? 16u : 0u;
    const uint32_t vrow = (lane & 7) + ((lane & 8) ? 8u : 0u);
    const uint32_t vck  = (lane & 16) ? 16u : 0u;

    for (int kt = 0; kt <= qt; kt++) {
        const int buf = kt & 1;
        __syncthreads();
        if (kt + 1 <= qt) {
            attn_load_kv(sb, buf ^ 1, boff, kt + 1, tid);
            asm volatile("cp.async.commit_group;" ::: "memory");
            asm volatile("cp.async.wait_group 1;" ::: "memory");
        } else {
            asm volatile("cp.async.wait_group 0;" ::: "memory");
        }
        __syncthreads();

        const uint32_t kvb = sb + AKV0 + buf * AKV_STRIDE;

        float sc[8][4];
#pragma unroll
        for (int j = 0; j < 8; j++)
#pragma unroll
            for (int q = 0; q < 4; q++) sc[j][q] = 0.f;

#pragma unroll
        for (int kk = 0; kk < 4; kk++) {
#pragma unroll
            for (int j2 = 0; j2 < 4; j2++) {
                uint32_t off = swz((j2 * 16 + brow) * 128 + kk * 32 + bck);
                uint32_t kh[4];
                LDSM4(kh[0], kh[1], kh[2], kh[3], kvb + AKH + off);
                MMA_F16(sc[2 * j2],     qf[kk], kh[0], kh[1]);
                MMA_F16(sc[2 * j2 + 1], qf[kk], kh[2], kh[3]);
            }
        }

        if ((kt == qt) || ((kt + 1) * 64 > S_)) {
            const int cb = kt * 64 + (lane & 3) * 2;
#pragma unroll
            for (int j = 0; j < 8; j++) {
                const int c0 = cb + j * 8, c1 = c0 + 1;
                if (c0 > row0 || c0 >= S_) sc[j][0] = -1e30f;
                if (c1 > row0 || c1 >= S_) sc[j][1] = -1e30f;
                if (c0 > row1 || c0 >= S_) sc[j][2] = -1e30f;
                if (c1 > row1 || c1 >= S_) sc[j][3] = -1e30f;
            }
        }

        float mt0 = -1e30f, mt1 = -1e30f;
#pragma unroll
        for (int j = 0; j < 8; j++) {
            mt0 = fmaxf(mt0, fmaxf(sc[j][0], sc[j][1]));
            mt1 = fmaxf(mt1, fmaxf(sc[j][2], sc[j][3]));
        }
        mt0 = fmaxf(mt0, __shfl_xor_sync(0xffffffffu, mt0, 1));
        mt0 = fmaxf(mt0, __shfl_xor_sync(0xffffffffu, mt0, 2));
        mt1 = fmaxf(mt1, __shfl_xor_sync(0xffffffffu, mt1, 1));
        mt1 = fmaxf(mt1, __shfl_xor_sync(0xffffffffu, mt1, 2));
        const float mn0 = fmaxf(m0v, mt0), mn1 = fmaxf(m1v, mt1);
        const float cr0 = exp2f(m0v - mn0), cr1 = exp2f(m1v - mn1);
        m0v = mn0; m1v = mn1;

        uint32_t ph[8][2];
#pragma unroll
        for (int j = 0; j < 8; j++) {
            __half2 a0 = __floats2half2_rn(sc[j][0] - mn0, sc[j][1] - mn0);
            __half2 a1 = __floats2half2_rn(sc[j][2] - mn1, sc[j][3] - mn1);
            __half2 e0 = h2exp2(a0);
            __half2 e1 = h2exp2(a1);
            ph[j][0] = *(uint32_t*)&e0;
            ph[j][1] = *(uint32_t*)&e1;
        }

        lsum[0] *= cr0; lsum[1] *= cr0; lsum[2] *= cr1; lsum[3] *= cr1;
#pragma unroll
        for (int dn = 0; dn < 8; dn++) {
            o[dn][0] *= cr0; o[dn][1] *= cr0;
            o[dn][2] *= cr1; o[dn][3] *= cr1;
        }

#pragma unroll
        for (int kk = 0; kk < 4; kk++) {
            uint32_t ah[4] = {ph[2 * kk][0], ph[2 * kk][1],
                              ph[2 * kk + 1][0], ph[2 * kk + 1][1]};
            MMA_F16(lsum, ah, ONE2, ONE2);
#pragma unroll
            for (int dj2 = 0; dj2 < 4; dj2++) {
                uint32_t off = swz((kk * 16 + vrow) * 128 + dj2 * 32 + vck);
                uint32_t vh[4];
                LDSM4T(vh[0], vh[1], vh[2], vh[3], kvb + AVH + off);
                MMA_F16(o[2 * dj2],     ah, vh[0], vh[1]);
                MMA_F16(o[2 * dj2 + 1], ah, vh[2], vh[3]);
            }
        }
    }

    const int h = bh & (H_ - 1);
    const int b = bh >> 4;
    const float inv0 = 1.f / lsum[0], inv1 = 1.f / lsum[2];
    const int dc = (lane & 3) * 2;
#pragma unroll
    for (int dn = 0; dn < 8; dn++) {
        const int d = h * D_ + dn * 8 + dc;
        if (row0 < S_) {
            size_t i0 = (size_t)(b * S_ + row0) * C_ + d;
            *(__half2*)(g_yh + i0) = __floats2half2_rn(o[dn][0] * inv0,
                                                       o[dn][1] * inv0);
        }
        if (row1 < S_) {
            size_t i1 = (size_t)(b * S_ + row1) * C_ + d;
            *(__half2*)(g_yh + i1) = __floats2half2_rn(o[dn][2] * inv1,
                                                       o[dn][3] * inv1);
        }
    }
}

// ---------------------------------------------------------------------------
extern "C" void kernel_launch(void* const* d_in, const int* in_sizes, int n_in,
                              void* d_out, int out_size)
{
    const float* x  = (const float*)d_in[0];
    const float* Wq = (const float*)d_in[1];
    const float* bq = (const float*)d_in[2];
    const float* Wk = (const float*)d_in[3];
    const float* bk = (const float*)d_in[4];
    const float* Wv = (const float*)d_in[5];
    const float* bv = (const float*)d_in[6];
    const float* Wp = (const float*)d_in[7];
    const float* bp = (const float*)d_in[8];
    float* out = (float*)d_out;

    cudaFuncSetAttribute(qkv_mma, cudaFuncAttributeMaxDynamicSharedMemorySize, GSMEM);
    cudaFuncSetAttribute(proj_mma, cudaFuncAttributeMaxDynamicSharedMemorySize, GSMEM);
    cudaFuncSetAttribute(attn_mma, cudaFuncAttributeMaxDynamicSharedMemorySize, ASMEM);

    xcvt_kernel<<<M_ * C_ / 2048, 256>>>(x);
    wtrans_kernel<<<dim3(32, 32, 4), dim3(32, 8)>>>(Wq, Wk, Wv, Wp);
    qkv_mma<<<dim3(8, MT, 3), 512, GSMEM>>>(bq, bk, bv);
    attn_mma<<<dim3(8, BH_), 128, ASMEM>>>();
    proj_mma<<<dim3(8, MT), 512, GSMEM>>>(bp, out);
}